// round 2
// baseline (speedup 1.0000x reference)
#include <cuda_runtime.h>

#define NN 20000
#define EE 320000
#define DD 128
#define LL 5
#define EVV 5
#define BN_EPS 1e-5f

// ---------------- device scratch (no allocation allowed) ----------------
__device__ float g_h1[NN * DD];
__device__ float g_h2[NN * DD];
__device__ float g_A1[NN * DD];
__device__ float g_A2[NN * DD];
__device__ float g_Y1[NN * DD];
__device__ float g_Y2[NN * DD];
__device__ int   g_deg[NN];
__device__ int   g_off[NN + 1];
__device__ int   g_cur[NN];
__device__ int   g_srcp[EE];
__device__ int   g_eap[EE];
__device__ float g_sum[2 * DD];
__device__ float g_sq[2 * DD];

// ---------------- CSR build ----------------
__global__ void k_zero_deg() {
    int i = blockIdx.x * blockDim.x + threadIdx.x;
    if (i < NN) g_deg[i] = 0;
}

__global__ void k_hist(const int* __restrict__ ei) {
    int e = blockIdx.x * blockDim.x + threadIdx.x;
    if (e < EE) atomicAdd(&g_deg[ei[EE + e]], 1);
}

__global__ void k_scan() {
    __shared__ int sm[1024];
    __shared__ int carry;
    int tid = threadIdx.x;
    if (tid == 0) { carry = 0; g_off[0] = 0; }
    __syncthreads();
    for (int base = 0; base < NN; base += 1024) {
        int i = base + tid;
        int v = (i < NN) ? g_deg[i] : 0;
        sm[tid] = v;
        __syncthreads();
        for (int off = 1; off < 1024; off <<= 1) {
            int t = (tid >= off) ? sm[tid - off] : 0;
            __syncthreads();
            sm[tid] += t;
            __syncthreads();
        }
        if (i < NN) {
            int incl = carry + sm[tid];
            g_off[i + 1] = incl;
            g_cur[i] = incl - v;
        }
        __syncthreads();
        if (tid == 1023) carry += sm[1023];
        __syncthreads();
    }
}

__global__ void k_scatter(const int* __restrict__ ei, const int* __restrict__ ea) {
    int e = blockIdx.x * blockDim.x + threadIdx.x;
    if (e < EE) {
        int d = ei[EE + e];
        int p = atomicAdd(&g_cur[d], 1);
        g_srcp[p] = ei[e];
        g_eap[p] = ea[e];
    }
}

// ---------------- node encoding ----------------
__global__ void k_encode(const int* __restrict__ x,
                         const float* __restrict__ ne1,
                         const float* __restrict__ ne2) {
    int idx = blockIdx.x * blockDim.x + threadIdx.x;
    if (idx >= NN * 32) return;
    int n = idx >> 5, c = idx & 31;
    int xv = x[n];
    ((float4*)g_h1)[n * 32 + c] = ((const float4*)ne1)[xv * 32 + c];
    ((float4*)g_h2)[n * 32 + c] = ((const float4*)ne2)[xv * 32 + c];
}

// ---------------- gather-based GIN aggregation (no fp atomics) ----------------
__global__ void k_aggregate(const float* __restrict__ et1,
                            const float* __restrict__ et2,
                            const float* __restrict__ eps_ptr, int layer) {
    __shared__ float4 s_et[2 * EVV * 32];   // 5 KB: both edge tables
    int tid = threadIdx.x;
    for (int i = tid; i < 2 * EVV * 32; i += blockDim.x) {
        if (i < EVV * 32) s_et[i] = ((const float4*)et1)[i];
        else              s_et[i] = ((const float4*)et2)[i - EVV * 32];
    }
    if (blockIdx.x == 0) {  // zero BN stat accumulators for this layer
        for (int i = tid; i < 4 * DD; i += blockDim.x) {
            if (i < 2 * DD) g_sum[i] = 0.f;
            else            g_sq[i - 2 * DD] = 0.f;
        }
    }
    __syncthreads();

    int warp = tid >> 5, lane = tid & 31;
    int n = blockIdx.x * (blockDim.x >> 5) + warp;
    if (n >= NN) return;

    int beg = g_off[n], end = g_off[n + 1];
    float4 acc1 = make_float4(0.f, 0.f, 0.f, 0.f);
    float4 acc2 = make_float4(0.f, 0.f, 0.f, 0.f);
    const float4* h1v = (const float4*)g_h1;
    const float4* h2v = (const float4*)g_h2;

    for (int e = beg; e < end; e++) {
        int s = g_srcp[e];
        int a = g_eap[e];
        float4 v1 = h1v[s * 32 + lane];
        float4 t1 = s_et[a * 32 + lane];
        acc1.x += fmaxf(v1.x + t1.x, 0.f);
        acc1.y += fmaxf(v1.y + t1.y, 0.f);
        acc1.z += fmaxf(v1.z + t1.z, 0.f);
        acc1.w += fmaxf(v1.w + t1.w, 0.f);
        float4 v2 = h2v[s * 32 + lane];
        float4 t2 = s_et[EVV * 32 + a * 32 + lane];
        acc2.x += fmaxf(v2.x + t2.x, 0.f);
        acc2.y += fmaxf(v2.y + t2.y, 0.f);
        acc2.z += fmaxf(v2.z + t2.z, 0.f);
        acc2.w += fmaxf(v2.w + t2.w, 0.f);
    }
    float e1 = 1.f + eps_ptr[layer];         // eps[0, l]
    float e2 = 1.f + eps_ptr[LL + layer];    // eps[1, l]
    float4 o1 = h1v[n * 32 + lane];
    float4 o2 = h2v[n * 32 + lane];
    float4 r1 = make_float4(e1 * o1.x + acc1.x, e1 * o1.y + acc1.y,
                            e1 * o1.z + acc1.z, e1 * o1.w + acc1.w);
    float4 r2 = make_float4(e2 * o2.x + acc2.x, e2 * o2.y + acc2.y,
                            e2 * o2.z + acc2.z, e2 * o2.w + acc2.w);
    ((float4*)g_A1)[n * 32 + lane] = r1;
    ((float4*)g_A2)[n * 32 + lane] = r2;
}

// ---------------- SGEMM: Y = A @ W^T + b, with fused BN stat accumulation ----
#define BM 128
#define BK 16
#define LDT 132   // padded smem leading dim

__global__ __launch_bounds__(256, 2) void k_gemm(const float* __restrict__ Wfull,
                                                 const float* __restrict__ bfull,
                                                 int layer) {
    __shared__ float sA[BK][LDT];
    __shared__ float sW[BK][LDT];

    int t = blockIdx.y;
    const float* A = t ? g_A2 : g_A1;
    float* Y = t ? g_Y2 : g_Y1;
    const float* Wp = Wfull + (t * LL + layer) * DD * DD;
    const float* bp = bfull + (t * LL + layer) * DD;

    int tid = threadIdx.x;
    int ty = tid >> 4, tx = tid & 15;   // 16x16 thread grid, 8x8 microtile
    int m0 = blockIdx.x * BM;

    float c[8][8];
#pragma unroll
    for (int i = 0; i < 8; i++)
#pragma unroll
        for (int j = 0; j < 8; j++) c[i][j] = 0.f;

    for (int k0 = 0; k0 < DD; k0 += BK) {
#pragma unroll
        for (int it = 0; it < 2; it++) {
            int idx = tid + it * 256;     // 0..511
            int row = idx >> 2;
            int col4 = (idx & 3) * 4;
            // A tile (guard rows past N)
            float4 va = make_float4(0.f, 0.f, 0.f, 0.f);
            if (m0 + row < NN)
                va = *(const float4*)&A[(m0 + row) * DD + k0 + col4];
            sA[col4 + 0][row] = va.x;
            sA[col4 + 1][row] = va.y;
            sA[col4 + 2][row] = va.z;
            sA[col4 + 3][row] = va.w;
            // W tile (row = output feature j, always valid)
            float4 vw = *(const float4*)&Wp[row * DD + k0 + col4];
            sW[col4 + 0][row] = vw.x;
            sW[col4 + 1][row] = vw.y;
            sW[col4 + 2][row] = vw.z;
            sW[col4 + 3][row] = vw.w;
        }
        __syncthreads();
#pragma unroll
        for (int kk = 0; kk < BK; kk++) {
            float af[8], wf[8];
            *(float4*)&af[0] = *(const float4*)&sA[kk][ty * 8];
            *(float4*)&af[4] = *(const float4*)&sA[kk][ty * 8 + 4];
            *(float4*)&wf[0] = *(const float4*)&sW[kk][tx * 8];
            *(float4*)&wf[4] = *(const float4*)&sW[kk][tx * 8 + 4];
#pragma unroll
            for (int i = 0; i < 8; i++)
#pragma unroll
                for (int j = 0; j < 8; j++) c[i][j] += af[i] * wf[j];
        }
        __syncthreads();
    }

    // epilogue: bias, store, per-feature partial sums for BN
    float bb[8];
    *(float4*)&bb[0] = *(const float4*)&bp[tx * 8];
    *(float4*)&bb[4] = *(const float4*)&bp[tx * 8 + 4];

    float psum[8], psq[8];
#pragma unroll
    for (int j = 0; j < 8; j++) { psum[j] = 0.f; psq[j] = 0.f; }

#pragma unroll
    for (int i = 0; i < 8; i++) {
        int m = m0 + ty * 8 + i;
        if (m < NN) {
            float y[8];
#pragma unroll
            for (int j = 0; j < 8; j++) {
                y[j] = c[i][j] + bb[j];
                psum[j] += y[j];
                psq[j] += y[j] * y[j];
            }
            *(float4*)&Y[m * DD + tx * 8] = *(float4*)&y[0];
            *(float4*)&Y[m * DD + tx * 8 + 4] = *(float4*)&y[4];
        }
    }

    // block reduce over ty, then one atomic per feature
    float* red = &sA[0][0];   // 16*128 <= 16*132 floats available
    __syncthreads();
#pragma unroll
    for (int j = 0; j < 8; j++) red[ty * DD + tx * 8 + j] = psum[j];
    __syncthreads();
    if (tid < DD) {
        float s = 0.f;
#pragma unroll
        for (int r = 0; r < 16; r++) s += red[r * DD + tid];
        atomicAdd(&g_sum[t * DD + tid], s);
    }
    __syncthreads();
#pragma unroll
    for (int j = 0; j < 8; j++) red[ty * DD + tx * 8 + j] = psq[j];
    __syncthreads();
    if (tid < DD) {
        float s = 0.f;
#pragma unroll
        for (int r = 0; r < 16; r++) s += red[r * DD + tid];
        atomicAdd(&g_sq[t * DD + tid], s);
    }
}

// ---------------- BN + relu + cross-stitch ----------------
__global__ void k_bn_cross(const float* __restrict__ gam,
                           const float* __restrict__ bet,
                           const float* __restrict__ cu,
                           int layer, int last, float* __restrict__ out) {
    int idx = blockIdx.x * blockDim.x + threadIdx.x;
    if (idx >= NN * 32) return;
    int n = idx >> 5, c4 = idx & 31;
    int f = c4 * 4;
    const float inv = 1.f / (float)NN;

    float4 s1 = *(const float4*)&g_sum[f];
    float4 q1 = *(const float4*)&g_sq[f];
    float4 s2 = *(const float4*)&g_sum[DD + f];
    float4 q2 = *(const float4*)&g_sq[DD + f];

    float4 mu1 = make_float4(s1.x * inv, s1.y * inv, s1.z * inv, s1.w * inv);
    float4 mu2 = make_float4(s2.x * inv, s2.y * inv, s2.z * inv, s2.w * inv);
    float4 rs1 = make_float4(rsqrtf(q1.x * inv - mu1.x * mu1.x + BN_EPS),
                             rsqrtf(q1.y * inv - mu1.y * mu1.y + BN_EPS),
                             rsqrtf(q1.z * inv - mu1.z * mu1.z + BN_EPS),
                             rsqrtf(q1.w * inv - mu1.w * mu1.w + BN_EPS));
    float4 rs2 = make_float4(rsqrtf(q2.x * inv - mu2.x * mu2.x + BN_EPS),
                             rsqrtf(q2.y * inv - mu2.y * mu2.y + BN_EPS),
                             rsqrtf(q2.z * inv - mu2.z * mu2.z + BN_EPS),
                             rsqrtf(q2.w * inv - mu2.w * mu2.w + BN_EPS));

    float4 g1 = *(const float4*)&gam[(0 * LL + layer) * DD + f];
    float4 b1 = *(const float4*)&bet[(0 * LL + layer) * DD + f];
    float4 g2 = *(const float4*)&gam[(1 * LL + layer) * DD + f];
    float4 b2 = *(const float4*)&bet[(1 * LL + layer) * DD + f];

    float4 y1 = ((const float4*)g_Y1)[n * 32 + c4];
    float4 y2 = ((const float4*)g_Y2)[n * 32 + c4];

    y1.x = (y1.x - mu1.x) * rs1.x * g1.x + b1.x;
    y1.y = (y1.y - mu1.y) * rs1.y * g1.y + b1.y;
    y1.z = (y1.z - mu1.z) * rs1.z * g1.z + b1.z;
    y1.w = (y1.w - mu1.w) * rs1.w * g1.w + b1.w;
    y2.x = (y2.x - mu2.x) * rs2.x * g2.x + b2.x;
    y2.y = (y2.y - mu2.y) * rs2.y * g2.y + b2.y;
    y2.z = (y2.z - mu2.z) * rs2.z * g2.z + b2.z;
    y2.w = (y2.w - mu2.w) * rs2.w * g2.w + b2.w;

    if (!last) {
        y1.x = fmaxf(y1.x, 0.f); y1.y = fmaxf(y1.y, 0.f);
        y1.z = fmaxf(y1.z, 0.f); y1.w = fmaxf(y1.w, 0.f);
        y2.x = fmaxf(y2.x, 0.f); y2.y = fmaxf(y2.y, 0.f);
        y2.z = fmaxf(y2.z, 0.f); y2.w = fmaxf(y2.w, 0.f);
    }

    float c00 = cu[layer * 4 + 0], c01 = cu[layer * 4 + 1];
    float c10 = cu[layer * 4 + 2], c11 = cu[layer * 4 + 3];

    float4 n1 = make_float4(c00 * y1.x + c01 * y2.x, c00 * y1.y + c01 * y2.y,
                            c00 * y1.z + c01 * y2.z, c00 * y1.w + c01 * y2.w);
    float4 n2 = make_float4(c10 * n1.x + c11 * y2.x, c10 * n1.y + c11 * y2.y,
                            c10 * n1.z + c11 * y2.z, c10 * n1.w + c11 * y2.w);

    if (last) {
        ((float4*)out)[n * 32 + c4] = n1;
        ((float4*)out)[NN * 32 + n * 32 + c4] = n2;
    } else {
        ((float4*)g_h1)[n * 32 + c4] = n1;
        ((float4*)g_h2)[n * 32 + c4] = n2;
    }
}

// ---------------- launch ----------------
extern "C" void kernel_launch(void* const* d_in, const int* in_sizes, int n_in,
                              void* d_out, int out_size) {
    const int* x = (const int*)d_in[0];
    const int* ei = (const int*)d_in[1];
    const int* ea = (const int*)d_in[2];
    const float* ne1 = (const float*)d_in[3];
    const float* ne2 = (const float*)d_in[4];
    const float* eemb = (const float*)d_in[5];
    const float* eps = (const float*)d_in[6];
    const float* W = (const float*)d_in[7];
    const float* b = (const float*)d_in[8];
    const float* gam = (const float*)d_in[9];
    const float* bet = (const float*)d_in[10];
    const float* cu = (const float*)d_in[11];
    float* out = (float*)d_out;

    k_zero_deg<<<(NN + 255) / 256, 256>>>();
    k_hist<<<(EE + 255) / 256, 256>>>(ei);
    k_scan<<<1, 1024>>>();
    k_scatter<<<(EE + 255) / 256, 256>>>(ei, ea);
    k_encode<<<(NN * 32 + 255) / 256, 256>>>(x, ne1, ne2);

    for (int l = 0; l < LL; l++) {
        k_aggregate<<<(NN + 7) / 8, 256>>>(eemb + (0 * LL + l) * EVV * DD,
                                           eemb + (1 * LL + l) * EVV * DD, eps, l);
        dim3 gg((NN + BM - 1) / BM, 2);
        k_gemm<<<gg, 256>>>(W, b, l);
        k_bn_cross<<<(NN * 32 + 255) / 256, 256>>>(gam, bet, cu, l, (l == LL - 1) ? 1 : 0, out);
    }
}

// round 4
// speedup vs baseline: 1.2878x; 1.2878x over previous
#include <cuda_runtime.h>
#include <cuda_bf16.h>
#include <cstdint>

#define NN 20000
#define EE 320000
#define DD 128
#define LL 5
#define EVV 5
#define BN_EPS 1e-5f

// ---------------- device scratch (no allocation allowed) ----------------
__device__ float g_h1[NN * DD];
__device__ float g_h2[NN * DD];
__device__ float g_A1[NN * DD];
__device__ float g_A2[NN * DD];
__device__ float g_Y1[NN * DD];
__device__ float g_Y2[NN * DD];
__device__ int   g_deg[NN];
__device__ int   g_off[NN + 1];
__device__ int   g_cur[NN];
__device__ int   g_srcp[EE];
__device__ int   g_eap[EE];
__device__ float g_sum[2 * DD];
__device__ float g_sq[2 * DD];

// ---------------- PTX helpers ----------------
__device__ __forceinline__ uint32_t smem_u32(const void* p) {
    uint32_t a;
    asm("{ .reg .u64 t; cvta.to.shared.u64 t, %1; cvt.u32.u64 %0, t; }" : "=r"(a) : "l"(p));
    return a;
}
__device__ __forceinline__ void ldsm4(uint32_t* r, uint32_t addr) {
    asm volatile("ldmatrix.sync.aligned.m8n8.x4.shared.b16 {%0,%1,%2,%3}, [%4];"
                 : "=r"(r[0]), "=r"(r[1]), "=r"(r[2]), "=r"(r[3]) : "r"(addr));
}
__device__ __forceinline__ void mma16816(float* d, const uint32_t* a, const uint32_t* b) {
    asm volatile(
        "mma.sync.aligned.m16n8k16.row.col.f32.bf16.bf16.f32 "
        "{%0,%1,%2,%3}, {%4,%5,%6,%7}, {%8,%9}, {%0,%1,%2,%3};"
        : "+f"(d[0]), "+f"(d[1]), "+f"(d[2]), "+f"(d[3])
        : "r"(a[0]), "r"(a[1]), "r"(a[2]), "r"(a[3]), "r"(b[0]), "r"(b[1]));
}

// ---------------- CSR build ----------------
__global__ void k_zero_deg() {
    int i = blockIdx.x * blockDim.x + threadIdx.x;
    if (i < NN) g_deg[i] = 0;
}

__global__ void k_hist(const int* __restrict__ ei) {
    int e = blockIdx.x * blockDim.x + threadIdx.x;
    if (e < EE) atomicAdd(&g_deg[ei[EE + e]], 1);
}

__global__ void k_scan() {
    __shared__ int sm[1024];
    __shared__ int carry;
    int tid = threadIdx.x;
    if (tid == 0) { carry = 0; g_off[0] = 0; }
    __syncthreads();
    for (int base = 0; base < NN; base += 1024) {
        int i = base + tid;
        int v = (i < NN) ? g_deg[i] : 0;
        sm[tid] = v;
        __syncthreads();
        for (int off = 1; off < 1024; off <<= 1) {
            int t = (tid >= off) ? sm[tid - off] : 0;
            __syncthreads();
            sm[tid] += t;
            __syncthreads();
        }
        if (i < NN) {
            int incl = carry + sm[tid];
            g_off[i + 1] = incl;
            g_cur[i] = incl - v;
        }
        __syncthreads();
        if (tid == 1023) carry += sm[1023];
        __syncthreads();
    }
}

__global__ void k_scatter(const int* __restrict__ ei, const int* __restrict__ ea) {
    int e = blockIdx.x * blockDim.x + threadIdx.x;
    if (e < EE) {
        int d = ei[EE + e];
        int p = atomicAdd(&g_cur[d], 1);
        g_srcp[p] = ei[e];
        g_eap[p] = ea[e];
    }
}

// ---------------- node encoding ----------------
__global__ void k_encode(const int* __restrict__ x,
                         const float* __restrict__ ne1,
                         const float* __restrict__ ne2) {
    int idx = blockIdx.x * blockDim.x + threadIdx.x;
    if (idx >= NN * 32) return;
    int n = idx >> 5, c = idx & 31;
    int xv = x[n];
    ((float4*)g_h1)[n * 32 + c] = ((const float4*)ne1)[xv * 32 + c];
    ((float4*)g_h2)[n * 32 + c] = ((const float4*)ne2)[xv * 32 + c];
}

// ---------------- gather-based GIN aggregation (no fp atomics) ----------------
__global__ void k_aggregate(const float* __restrict__ et1,
                            const float* __restrict__ et2,
                            const float* __restrict__ eps_ptr, int layer) {
    __shared__ float4 s_et[2 * EVV * 32];   // 5 KB: both edge tables
    int tid = threadIdx.x;
    for (int i = tid; i < 2 * EVV * 32; i += blockDim.x) {
        if (i < EVV * 32) s_et[i] = ((const float4*)et1)[i];
        else              s_et[i] = ((const float4*)et2)[i - EVV * 32];
    }
    if (blockIdx.x == 0) {  // zero BN stat accumulators for this layer
        for (int i = tid; i < 4 * DD; i += blockDim.x) {
            if (i < 2 * DD) g_sum[i] = 0.f;
            else            g_sq[i - 2 * DD] = 0.f;
        }
    }
    __syncthreads();

    int warp = tid >> 5, lane = tid & 31;
    int n = blockIdx.x * (blockDim.x >> 5) + warp;
    if (n >= NN) return;

    int beg = g_off[n], end = g_off[n + 1];
    float4 acc1 = make_float4(0.f, 0.f, 0.f, 0.f);
    float4 acc2 = make_float4(0.f, 0.f, 0.f, 0.f);
    const float4* h1v = (const float4*)g_h1;
    const float4* h2v = (const float4*)g_h2;

#pragma unroll 2
    for (int e = beg; e < end; e++) {
        int s = __ldg(&g_srcp[e]);
        int a = __ldg(&g_eap[e]);
        float4 v1 = h1v[s * 32 + lane];
        float4 t1 = s_et[a * 32 + lane];
        acc1.x += fmaxf(v1.x + t1.x, 0.f);
        acc1.y += fmaxf(v1.y + t1.y, 0.f);
        acc1.z += fmaxf(v1.z + t1.z, 0.f);
        acc1.w += fmaxf(v1.w + t1.w, 0.f);
        float4 v2 = h2v[s * 32 + lane];
        float4 t2 = s_et[EVV * 32 + a * 32 + lane];
        acc2.x += fmaxf(v2.x + t2.x, 0.f);
        acc2.y += fmaxf(v2.y + t2.y, 0.f);
        acc2.z += fmaxf(v2.z + t2.z, 0.f);
        acc2.w += fmaxf(v2.w + t2.w, 0.f);
    }
    float e1 = 1.f + eps_ptr[layer];         // eps[0, l]
    float e2 = 1.f + eps_ptr[LL + layer];    // eps[1, l]
    float4 o1 = h1v[n * 32 + lane];
    float4 o2 = h2v[n * 32 + lane];
    float4 r1 = make_float4(e1 * o1.x + acc1.x, e1 * o1.y + acc1.y,
                            e1 * o1.z + acc1.z, e1 * o1.w + acc1.w);
    float4 r2 = make_float4(e2 * o2.x + acc2.x, e2 * o2.y + acc2.y,
                            e2 * o2.z + acc2.z, e2 * o2.w + acc2.w);
    ((float4*)g_A1)[n * 32 + lane] = r1;
    ((float4*)g_A2)[n * 32 + lane] = r2;
}

// ---------------- HMMA GEMM: Y = A @ W^T + b  (bf16 hi/lo x3, fp32 acc) ------
// SMEM (dynamic, 128KB): Ahi | Alo | Whi | Wlo, each 128 rows x 256B
// Row layout: 16 chunks of 16B; chunk' = chunk ^ (row & 7)  (conflict-free ldmatrix)
#define SM_AHI  0
#define SM_ALO  32768
#define SM_WHI  65536
#define SM_WLO  98304
#define SM_GEMM_TOTAL 131072

__global__ __launch_bounds__(256, 1) void k_gemm_tc(const float* __restrict__ Wfull,
                                                    const float* __restrict__ bfull,
                                                    int layer) {
    extern __shared__ char smem[];
    uint32_t sbase = smem_u32(smem);
    int tid = threadIdx.x;
    int wid = tid >> 5, lane = tid & 31;

    int t = blockIdx.y;
    const float* A = t ? g_A2 : g_A1;
    float* Y = t ? g_Y2 : g_Y1;
    const float* Wp = Wfull + (t * LL + layer) * DD * DD;
    const float* bp = bfull + (t * LL + layer) * DD;
    int m0 = blockIdx.x * 128;

    // Load fp32 tiles, split to bf16 hi/lo, store swizzled.
    for (int i = tid; i < 128 * 64; i += 256) {
        int row = i >> 6, cp = i & 63;           // cp: 4B unit (2 bf16)
        int chunk = cp >> 2, within = cp & 3;
        uint32_t so = (uint32_t)row * 256u + (uint32_t)((chunk ^ (row & 7)) << 4)
                    + (uint32_t)(within << 2);
        float2 va = (m0 + row < NN) ? *(const float2*)&A[(m0 + row) * DD + cp * 2]
                                    : make_float2(0.f, 0.f);
        __nv_bfloat16 ah0 = __float2bfloat16(va.x);
        __nv_bfloat16 ah1 = __float2bfloat16(va.y);
        __nv_bfloat16 al0 = __float2bfloat16(va.x - __bfloat162float(ah0));
        __nv_bfloat16 al1 = __float2bfloat16(va.y - __bfloat162float(ah1));
        *(uint32_t*)(smem + SM_AHI + so) =
            (uint32_t)__bfloat16_as_ushort(ah0) | ((uint32_t)__bfloat16_as_ushort(ah1) << 16);
        *(uint32_t*)(smem + SM_ALO + so) =
            (uint32_t)__bfloat16_as_ushort(al0) | ((uint32_t)__bfloat16_as_ushort(al1) << 16);
        float2 vw = *(const float2*)&Wp[row * DD + cp * 2];
        __nv_bfloat16 wh0 = __float2bfloat16(vw.x);
        __nv_bfloat16 wh1 = __float2bfloat16(vw.y);
        __nv_bfloat16 wl0 = __float2bfloat16(vw.x - __bfloat162float(wh0));
        __nv_bfloat16 wl1 = __float2bfloat16(vw.y - __bfloat162float(wh1));
        *(uint32_t*)(smem + SM_WHI + so) =
            (uint32_t)__bfloat16_as_ushort(wh0) | ((uint32_t)__bfloat16_as_ushort(wh1) << 16);
        *(uint32_t*)(smem + SM_WLO + so) =
            (uint32_t)__bfloat16_as_ushort(wl0) | ((uint32_t)__bfloat16_as_ushort(wl1) << 16);
    }
    __syncthreads();

    // warp tiling: 4 (m) x 2 (n); warp tile 32x64
    int wm = wid & 3, wn = wid >> 2;
    int grp = lane >> 3, r8 = lane & 7;

    // ldmatrix row indices (row & 7 == r8 for all)
    int a_row0 = wm * 32 + (grp & 1) * 8 + r8;          // + i*16
    int b_row0 = wn * 64 + (grp >> 1) * 8 + r8;         // + jj*16
    int kselA = grp >> 1;                               // k-chunk parity for A
    int kselB = grp & 1;                                // k-chunk parity for B

    float acc[2][8][4];
#pragma unroll
    for (int i = 0; i < 2; i++)
#pragma unroll
        for (int j = 0; j < 8; j++)
#pragma unroll
            for (int q = 0; q < 4; q++) acc[i][j][q] = 0.f;

#pragma unroll
    for (int p = 0; p < 3; p++) {
        uint32_t Ab = sbase + ((p == 2) ? SM_ALO : SM_AHI);
        uint32_t Bb = sbase + ((p == 1) ? SM_WLO : SM_WHI);
#pragma unroll
        for (int ks = 0; ks < 8; ks++) {
            uint32_t af[2][4], bf[4][4];
            uint32_t aoff = (uint32_t)(((ks * 2 + kselA) ^ r8) << 4);
            ldsm4(af[0], Ab + (uint32_t)a_row0 * 256u + aoff);
            ldsm4(af[1], Ab + (uint32_t)(a_row0 + 16) * 256u + aoff);
            uint32_t boff = (uint32_t)(((ks * 2 + kselB) ^ r8) << 4);
#pragma unroll
            for (int jj = 0; jj < 4; jj++)
                ldsm4(bf[jj], Bb + (uint32_t)(b_row0 + jj * 16) * 256u + boff);
#pragma unroll
            for (int i = 0; i < 2; i++)
#pragma unroll
                for (int j = 0; j < 8; j++)
                    mma16816(acc[i][j], af[i], &bf[j >> 1][(j & 1) * 2]);
        }
    }

    // Epilogue: bias add, store Y, fused BN partial sums
    int qr = lane >> 2, qc = lane & 3;   // d-frag: rows qr/+8, cols qc*2/+1
#pragma unroll
    for (int j = 0; j < 8; j++) {
        int c0 = wn * 64 + j * 8 + qc * 2;
        float bb0 = bp[c0], bb1 = bp[c0 + 1];
        float s0 = 0.f, s1 = 0.f, q0 = 0.f, q1 = 0.f;
#pragma unroll
        for (int i = 0; i < 2; i++) {
#pragma unroll
            for (int h = 0; h < 2; h++) {
                int m = m0 + wm * 32 + i * 16 + qr + h * 8;
                float v0 = acc[i][j][h * 2 + 0] + bb0;
                float v1 = acc[i][j][h * 2 + 1] + bb1;
                if (m < NN) {
                    *(float2*)&Y[m * DD + c0] = make_float2(v0, v1);
                    s0 += v0; s1 += v1;
                    q0 += v0 * v0; q1 += v1 * v1;
                }
            }
        }
#pragma unroll
        for (int off = 4; off < 32; off <<= 1) {
            s0 += __shfl_xor_sync(0xffffffffu, s0, off);
            s1 += __shfl_xor_sync(0xffffffffu, s1, off);
            q0 += __shfl_xor_sync(0xffffffffu, q0, off);
            q1 += __shfl_xor_sync(0xffffffffu, q1, off);
        }
        if (qr == 0) {
            atomicAdd(&g_sum[t * DD + c0], s0);
            atomicAdd(&g_sum[t * DD + c0 + 1], s1);
            atomicAdd(&g_sq[t * DD + c0], q0);
            atomicAdd(&g_sq[t * DD + c0 + 1], q1);
        }
    }
}

// ---------------- BN + relu + cross-stitch ----------------
__global__ void k_bn_cross(const float* __restrict__ gam,
                           const float* __restrict__ bet,
                           const float* __restrict__ cu,
                           int layer, int last, float* __restrict__ out) {
    int idx = blockIdx.x * blockDim.x + threadIdx.x;
    if (idx >= NN * 32) return;
    int n = idx >> 5, c4 = idx & 31;
    int f = c4 * 4;
    const float inv = 1.f / (float)NN;

    float4 s1 = *(const float4*)&g_sum[f];
    float4 q1 = *(const float4*)&g_sq[f];
    float4 s2 = *(const float4*)&g_sum[DD + f];
    float4 q2 = *(const float4*)&g_sq[DD + f];

    float4 mu1 = make_float4(s1.x * inv, s1.y * inv, s1.z * inv, s1.w * inv);
    float4 mu2 = make_float4(s2.x * inv, s2.y * inv, s2.z * inv, s2.w * inv);
    float4 rs1 = make_float4(rsqrtf(q1.x * inv - mu1.x * mu1.x + BN_EPS),
                             rsqrtf(q1.y * inv - mu1.y * mu1.y + BN_EPS),
                             rsqrtf(q1.z * inv - mu1.z * mu1.z + BN_EPS),
                             rsqrtf(q1.w * inv - mu1.w * mu1.w + BN_EPS));
    float4 rs2 = make_float4(rsqrtf(q2.x * inv - mu2.x * mu2.x + BN_EPS),
                             rsqrtf(q2.y * inv - mu2.y * mu2.y + BN_EPS),
                             rsqrtf(q2.z * inv - mu2.z * mu2.z + BN_EPS),
                             rsqrtf(q2.w * inv - mu2.w * mu2.w + BN_EPS));

    float4 g1 = *(const float4*)&gam[(0 * LL + layer) * DD + f];
    float4 b1 = *(const float4*)&bet[(0 * LL + layer) * DD + f];
    float4 g2 = *(const float4*)&gam[(1 * LL + layer) * DD + f];
    float4 b2 = *(const float4*)&bet[(1 * LL + layer) * DD + f];

    float4 y1 = ((const float4*)g_Y1)[n * 32 + c4];
    float4 y2 = ((const float4*)g_Y2)[n * 32 + c4];

    y1.x = (y1.x - mu1.x) * rs1.x * g1.x + b1.x;
    y1.y = (y1.y - mu1.y) * rs1.y * g1.y + b1.y;
    y1.z = (y1.z - mu1.z) * rs1.z * g1.z + b1.z;
    y1.w = (y1.w - mu1.w) * rs1.w * g1.w + b1.w;
    y2.x = (y2.x - mu2.x) * rs2.x * g2.x + b2.x;
    y2.y = (y2.y - mu2.y) * rs2.y * g2.y + b2.y;
    y2.z = (y2.z - mu2.z) * rs2.z * g2.z + b2.z;
    y2.w = (y2.w - mu2.w) * rs2.w * g2.w + b2.w;

    if (!last) {
        y1.x = fmaxf(y1.x, 0.f); y1.y = fmaxf(y1.y, 0.f);
        y1.z = fmaxf(y1.z, 0.f); y1.w = fmaxf(y1.w, 0.f);
        y2.x = fmaxf(y2.x, 0.f); y2.y = fmaxf(y2.y, 0.f);
        y2.z = fmaxf(y2.z, 0.f); y2.w = fmaxf(y2.w, 0.f);
    }

    float c00 = cu[layer * 4 + 0], c01 = cu[layer * 4 + 1];
    float c10 = cu[layer * 4 + 2], c11 = cu[layer * 4 + 3];

    float4 n1 = make_float4(c00 * y1.x + c01 * y2.x, c00 * y1.y + c01 * y2.y,
                            c00 * y1.z + c01 * y2.z, c00 * y1.w + c01 * y2.w);
    float4 n2 = make_float4(c10 * n1.x + c11 * y2.x, c10 * n1.y + c11 * y2.y,
                            c10 * n1.z + c11 * y2.z, c10 * n1.w + c11 * y2.w);

    if (last) {
        ((float4*)out)[n * 32 + c4] = n1;
        ((float4*)out)[NN * 32 + n * 32 + c4] = n2;
    } else {
        ((float4*)g_h1)[n * 32 + c4] = n1;
        ((float4*)g_h2)[n * 32 + c4] = n2;
    }
}

// ---------------- launch ----------------
extern "C" void kernel_launch(void* const* d_in, const int* in_sizes, int n_in,
                              void* d_out, int out_size) {
    const int* x = (const int*)d_in[0];
    const int* ei = (const int*)d_in[1];
    const int* ea = (const int*)d_in[2];
    const float* ne1 = (const float*)d_in[3];
    const float* ne2 = (const float*)d_in[4];
    const float* eemb = (const float*)d_in[5];
    const float* eps = (const float*)d_in[6];
    const float* W = (const float*)d_in[7];
    const float* b = (const float*)d_in[8];
    const float* gam = (const float*)d_in[9];
    const float* bet = (const float*)d_in[10];
    const float* cu = (const float*)d_in[11];
    float* out = (float*)d_out;

    static int smem_set = 0;
    if (!smem_set) {
        cudaFuncSetAttribute(k_gemm_tc, cudaFuncAttributeMaxDynamicSharedMemorySize,
                             SM_GEMM_TOTAL);
        smem_set = 1;
    }

    k_zero_deg<<<(NN + 255) / 256, 256>>>();
    k_hist<<<(EE + 255) / 256, 256>>>(ei);
    k_scan<<<1, 1024>>>();
    k_scatter<<<(EE + 255) / 256, 256>>>(ei, ea);
    k_encode<<<(NN * 32 + 255) / 256, 256>>>(x, ne1, ne2);

    for (int l = 0; l < LL; l++) {
        k_aggregate<<<(NN + 7) / 8, 256>>>(eemb + (0 * LL + l) * EVV * DD,
                                           eemb + (1 * LL + l) * EVV * DD, eps, l);
        dim3 gg((NN + 127) / 128, 2);
        k_gemm_tc<<<gg, 256, SM_GEMM_TOTAL>>>(W, b, l);
        k_bn_cross<<<(NN * 32 + 255) / 256, 256>>>(gam, bet, cu, l, (l == LL - 1) ? 1 : 0, out);
    }
}

// round 5
// speedup vs baseline: 1.4607x; 1.1343x over previous
#include <cuda_runtime.h>
#include <cuda_bf16.h>
#include <cstdint>

#define NN 20000
#define EE 320000
#define DD 128
#define LL 5
#define EVV 5
#define BN_EPS 1e-5f
#define MPAD 20096   // 157 * 128

// ---------------- device scratch (no allocation allowed) ----------------
__device__ float g_h1[NN * DD];
__device__ float g_h2[NN * DD];
__device__ float g_Y1[NN * DD];
__device__ float g_Y2[NN * DD];
__device__ __nv_bfloat16 g_A1hi[MPAD * DD];
__device__ __nv_bfloat16 g_A1lo[MPAD * DD];
__device__ __nv_bfloat16 g_A2hi[MPAD * DD];
__device__ __nv_bfloat16 g_A2lo[MPAD * DD];
__device__ __nv_bfloat16 g_Whi[2 * LL * DD * DD];
__device__ __nv_bfloat16 g_Wlo[2 * LL * DD * DD];
__device__ int   g_deg[NN];
__device__ int   g_off[NN + 1];
__device__ int   g_cur[NN];
__device__ int   g_pack[EE];     // (src << 3) | attr
__device__ float g_sum[2 * DD];
__device__ float g_sq[2 * DD];

// ---------------- PTX helpers ----------------
__device__ __forceinline__ uint32_t smem_u32(const void* p) {
    uint32_t a;
    asm("{ .reg .u64 t; cvta.to.shared.u64 t, %1; cvt.u32.u64 %0, t; }" : "=r"(a) : "l"(p));
    return a;
}
__device__ __forceinline__ void ldsm4(uint32_t* r, uint32_t addr) {
    asm volatile("ldmatrix.sync.aligned.m8n8.x4.shared.b16 {%0,%1,%2,%3}, [%4];"
                 : "=r"(r[0]), "=r"(r[1]), "=r"(r[2]), "=r"(r[3]) : "r"(addr));
}
__device__ __forceinline__ void mma16816(float* d, const uint32_t* a, const uint32_t* b) {
    asm volatile(
        "mma.sync.aligned.m16n8k16.row.col.f32.bf16.bf16.f32 "
        "{%0,%1,%2,%3}, {%4,%5,%6,%7}, {%8,%9}, {%0,%1,%2,%3};"
        : "+f"(d[0]), "+f"(d[1]), "+f"(d[2]), "+f"(d[3])
        : "r"(a[0]), "r"(a[1]), "r"(a[2]), "r"(a[3]), "r"(b[0]), "r"(b[1]));
}
__device__ __forceinline__ void cp16(uint32_t dst, const void* src) {
    asm volatile("cp.async.cg.shared.global [%0], [%1], 16;" :: "r"(dst), "l"(src));
}
__device__ __forceinline__ void cp_commit_wait() {
    asm volatile("cp.async.commit_group;" ::: "memory");
    asm volatile("cp.async.wait_group 0;" ::: "memory");
}

// ---------------- CSR build ----------------
__global__ void k_zero_deg() {
    int i = blockIdx.x * blockDim.x + threadIdx.x;
    if (i < NN) g_deg[i] = 0;
}

__global__ void k_hist(const int* __restrict__ ei) {
    int e = blockIdx.x * blockDim.x + threadIdx.x;
    if (e < EE) atomicAdd(&g_deg[ei[EE + e]], 1);
}

__global__ void k_scan() {
    __shared__ int wsum[32];
    __shared__ int carry;
    int tid = threadIdx.x, lane = tid & 31, w = tid >> 5;
    if (tid == 0) { carry = 0; g_off[0] = 0; }
    __syncthreads();
    for (int base = 0; base < NN; base += 1024) {
        int i = base + tid;
        int v = (i < NN) ? g_deg[i] : 0;
        int x = v;
#pragma unroll
        for (int o = 1; o < 32; o <<= 1) {
            int y = __shfl_up_sync(0xffffffffu, x, o);
            if (lane >= o) x += y;
        }
        if (lane == 31) wsum[w] = x;
        __syncthreads();
        if (w == 0) {
            int s = wsum[lane];
#pragma unroll
            for (int o = 1; o < 32; o <<= 1) {
                int y = __shfl_up_sync(0xffffffffu, s, o);
                if (lane >= o) s += y;
            }
            wsum[lane] = s;
        }
        __syncthreads();
        int incl = x + (w ? wsum[w - 1] : 0) + carry;
        if (i < NN) { g_off[i + 1] = incl; g_cur[i] = incl - v; }
        __syncthreads();
        if (tid == 1023) carry = incl;
        __syncthreads();
    }
}

__global__ void k_scatter(const int* __restrict__ ei, const int* __restrict__ ea) {
    int e = blockIdx.x * blockDim.x + threadIdx.x;
    if (e < EE) {
        int d = ei[EE + e];
        int p = atomicAdd(&g_cur[d], 1);
        g_pack[p] = (ei[e] << 3) | ea[e];
    }
}

// ---------------- weight pre-conversion (fp32 -> bf16 hi/lo) ----------------
__global__ void k_convW(const float* __restrict__ Wfull) {
    int i = blockIdx.x * blockDim.x + threadIdx.x;
    if (i >= 2 * LL * DD * DD) return;
    float v = Wfull[i];
    __nv_bfloat16 h = __float2bfloat16(v);
    g_Whi[i] = h;
    g_Wlo[i] = __float2bfloat16(v - __bfloat162float(h));
}

// ---------------- node encoding ----------------
__global__ void k_encode(const int* __restrict__ x,
                         const float* __restrict__ ne1,
                         const float* __restrict__ ne2) {
    int idx = blockIdx.x * blockDim.x + threadIdx.x;
    if (idx >= NN * 32) return;
    int n = idx >> 5, c = idx & 31;
    int xv = x[n];
    ((float4*)g_h1)[n * 32 + c] = ((const float4*)ne1)[xv * 32 + c];
    ((float4*)g_h2)[n * 32 + c] = ((const float4*)ne2)[xv * 32 + c];
}

// ---------------- gather aggregation; writes A as bf16 hi/lo ----------------
__device__ __forceinline__ void split4(float4 r, uint2* hi, uint2* lo) {
    __nv_bfloat16 hx = __float2bfloat16(r.x), hy = __float2bfloat16(r.y);
    __nv_bfloat16 hz = __float2bfloat16(r.z), hw = __float2bfloat16(r.w);
    __nv_bfloat16 lx = __float2bfloat16(r.x - __bfloat162float(hx));
    __nv_bfloat16 ly = __float2bfloat16(r.y - __bfloat162float(hy));
    __nv_bfloat16 lz = __float2bfloat16(r.z - __bfloat162float(hz));
    __nv_bfloat16 lw = __float2bfloat16(r.w - __bfloat162float(hw));
    hi->x = (uint32_t)__bfloat16_as_ushort(hx) | ((uint32_t)__bfloat16_as_ushort(hy) << 16);
    hi->y = (uint32_t)__bfloat16_as_ushort(hz) | ((uint32_t)__bfloat16_as_ushort(hw) << 16);
    lo->x = (uint32_t)__bfloat16_as_ushort(lx) | ((uint32_t)__bfloat16_as_ushort(ly) << 16);
    lo->y = (uint32_t)__bfloat16_as_ushort(lz) | ((uint32_t)__bfloat16_as_ushort(lw) << 16);
}

__global__ void k_aggregate(const float* __restrict__ et1,
                            const float* __restrict__ et2,
                            const float* __restrict__ eps_ptr, int layer) {
    __shared__ float4 s_et[2 * EVV * 32];
    int tid = threadIdx.x;
    for (int i = tid; i < 2 * EVV * 32; i += blockDim.x) {
        if (i < EVV * 32) s_et[i] = ((const float4*)et1)[i];
        else              s_et[i] = ((const float4*)et2)[i - EVV * 32];
    }
    if (blockIdx.x == 0) {
        for (int i = tid; i < 4 * DD; i += blockDim.x) {
            if (i < 2 * DD) g_sum[i] = 0.f;
            else            g_sq[i - 2 * DD] = 0.f;
        }
    }
    __syncthreads();

    int warp = tid >> 5, lane = tid & 31;
    int n = blockIdx.x * (blockDim.x >> 5) + warp;
    if (n >= NN) return;

    int beg = g_off[n], end = g_off[n + 1], deg = end - beg;
    float4 acc1 = make_float4(0.f, 0.f, 0.f, 0.f);
    float4 acc2 = make_float4(0.f, 0.f, 0.f, 0.f);
    const float4* h1v = (const float4*)g_h1;
    const float4* h2v = (const float4*)g_h2;

    for (int base = 0; base < deg; base += 32) {
        int idx = base + lane;
        int pk = (idx < deg) ? __ldg(&g_pack[beg + idx]) : 0;
        int cnt = min(32, deg - base);
        for (int k = 0; k < cnt; k++) {
            int p = __shfl_sync(0xffffffffu, pk, k);
            int s = p >> 3, a = p & 7;
            float4 v1 = h1v[s * 32 + lane];
            float4 t1 = s_et[a * 32 + lane];
            float4 v2 = h2v[s * 32 + lane];
            float4 t2 = s_et[EVV * 32 + a * 32 + lane];
            acc1.x += fmaxf(v1.x + t1.x, 0.f);
            acc1.y += fmaxf(v1.y + t1.y, 0.f);
            acc1.z += fmaxf(v1.z + t1.z, 0.f);
            acc1.w += fmaxf(v1.w + t1.w, 0.f);
            acc2.x += fmaxf(v2.x + t2.x, 0.f);
            acc2.y += fmaxf(v2.y + t2.y, 0.f);
            acc2.z += fmaxf(v2.z + t2.z, 0.f);
            acc2.w += fmaxf(v2.w + t2.w, 0.f);
        }
    }
    float e1 = 1.f + eps_ptr[layer];
    float e2 = 1.f + eps_ptr[LL + layer];
    float4 o1 = h1v[n * 32 + lane];
    float4 o2 = h2v[n * 32 + lane];
    float4 r1 = make_float4(e1 * o1.x + acc1.x, e1 * o1.y + acc1.y,
                            e1 * o1.z + acc1.z, e1 * o1.w + acc1.w);
    float4 r2 = make_float4(e2 * o2.x + acc2.x, e2 * o2.y + acc2.y,
                            e2 * o2.z + acc2.z, e2 * o2.w + acc2.w);

    uint2 hi, lo;
    split4(r1, &hi, &lo);
    *(uint2*)&g_A1hi[n * DD + lane * 4] = hi;
    *(uint2*)&g_A1lo[n * DD + lane * 4] = lo;
    split4(r2, &hi, &lo);
    *(uint2*)&g_A2hi[n * DD + lane * 4] = hi;
    *(uint2*)&g_A2lo[n * DD + lane * 4] = lo;
}

// ---------------- HMMA GEMM: Y = A @ W^T + b  (bf16 hi/lo x3, fp32 acc) ------
// SMEM (128KB): Ahi | Alo | Whi | Wlo, each 128 rows x 256B
// Row layout: 16 chunks of 16B; chunk' = chunk ^ (row & 7)
#define SM_AHI  0
#define SM_ALO  32768
#define SM_WHI  65536
#define SM_WLO  98304
#define SM_GEMM_TOTAL 131072

__global__ __launch_bounds__(256, 1) void k_gemm_tc(const float* __restrict__ bfull,
                                                    int layer) {
    extern __shared__ char smem[];
    uint32_t sbase = smem_u32(smem);
    int tid = threadIdx.x;
    int wid = tid >> 5, lane = tid & 31;

    int t = blockIdx.y;
    const __nv_bfloat16* Ahi = t ? g_A2hi : g_A1hi;
    const __nv_bfloat16* Alo = t ? g_A2lo : g_A1lo;
    const __nv_bfloat16* Whi = g_Whi + (t * LL + layer) * DD * DD;
    const __nv_bfloat16* Wlo = g_Wlo + (t * LL + layer) * DD * DD;
    float* Y = t ? g_Y2 : g_Y1;
    const float* bp = bfull + (t * LL + layer) * DD;
    int m0 = blockIdx.x * 128;

    // cp.async load phase: 4 tiles x 2048 16B-chunks
    for (int i = tid; i < 2048; i += 256) {
        int row = i >> 4, ch = i & 15;
        uint32_t so = (uint32_t)row * 256u + (uint32_t)((ch ^ (row & 7)) << 4);
        const char* arow = (const char*)(Ahi + (size_t)(m0 + row) * DD) + ch * 16;
        const char* arol = (const char*)(Alo + (size_t)(m0 + row) * DD) + ch * 16;
        const char* wrow = (const char*)(Whi + (size_t)row * DD) + ch * 16;
        const char* wrol = (const char*)(Wlo + (size_t)row * DD) + ch * 16;
        cp16(sbase + SM_AHI + so, arow);
        cp16(sbase + SM_ALO + so, arol);
        cp16(sbase + SM_WHI + so, wrow);
        cp16(sbase + SM_WLO + so, wrol);
    }
    cp_commit_wait();
    __syncthreads();

    // warp tiling: 4 (m) x 2 (n); warp tile 32x64
    int wm = wid & 3, wn = wid >> 2;
    int grp = lane >> 3, r8 = lane & 7;
    int a_row0 = wm * 32 + (grp & 1) * 8 + r8;
    int b_row0 = wn * 64 + (grp >> 1) * 8 + r8;
    int kselA = grp >> 1;
    int kselB = grp & 1;

    float acc[2][8][4];
#pragma unroll
    for (int i = 0; i < 2; i++)
#pragma unroll
        for (int j = 0; j < 8; j++)
#pragma unroll
            for (int q = 0; q < 4; q++) acc[i][j][q] = 0.f;

#pragma unroll
    for (int p = 0; p < 3; p++) {
        uint32_t Ab = sbase + ((p == 2) ? SM_ALO : SM_AHI);
        uint32_t Bb = sbase + ((p == 1) ? SM_WLO : SM_WHI);
#pragma unroll
        for (int ks = 0; ks < 8; ks++) {
            uint32_t af[2][4], bf[4][4];
            uint32_t aoff = (uint32_t)(((ks * 2 + kselA) ^ r8) << 4);
            ldsm4(af[0], Ab + (uint32_t)a_row0 * 256u + aoff);
            ldsm4(af[1], Ab + (uint32_t)(a_row0 + 16) * 256u + aoff);
            uint32_t boff = (uint32_t)(((ks * 2 + kselB) ^ r8) << 4);
#pragma unroll
            for (int jj = 0; jj < 4; jj++)
                ldsm4(bf[jj], Bb + (uint32_t)(b_row0 + jj * 16) * 256u + boff);
#pragma unroll
            for (int i = 0; i < 2; i++)
#pragma unroll
                for (int j = 0; j < 8; j++)
                    mma16816(acc[i][j], af[i], &bf[j >> 1][(j & 1) * 2]);
        }
    }

    // Epilogue: bias add, store Y, fused BN partial sums
    int qr = lane >> 2, qc = lane & 3;
#pragma unroll
    for (int j = 0; j < 8; j++) {
        int c0 = wn * 64 + j * 8 + qc * 2;
        float bb0 = bp[c0], bb1 = bp[c0 + 1];
        float s0 = 0.f, s1 = 0.f, q0 = 0.f, q1 = 0.f;
#pragma unroll
        for (int i = 0; i < 2; i++) {
#pragma unroll
            for (int h = 0; h < 2; h++) {
                int m = m0 + wm * 32 + i * 16 + qr + h * 8;
                float v0 = acc[i][j][h * 2 + 0] + bb0;
                float v1 = acc[i][j][h * 2 + 1] + bb1;
                if (m < NN) {
                    *(float2*)&Y[m * DD + c0] = make_float2(v0, v1);
                    s0 += v0; s1 += v1;
                    q0 += v0 * v0; q1 += v1 * v1;
                }
            }
        }
#pragma unroll
        for (int off = 4; off < 32; off <<= 1) {
            s0 += __shfl_xor_sync(0xffffffffu, s0, off);
            s1 += __shfl_xor_sync(0xffffffffu, s1, off);
            q0 += __shfl_xor_sync(0xffffffffu, q0, off);
            q1 += __shfl_xor_sync(0xffffffffu, q1, off);
        }
        if (qr == 0) {
            atomicAdd(&g_sum[t * DD + c0], s0);
            atomicAdd(&g_sum[t * DD + c0 + 1], s1);
            atomicAdd(&g_sq[t * DD + c0], q0);
            atomicAdd(&g_sq[t * DD + c0 + 1], q1);
        }
    }
}

// ---------------- BN + relu + cross-stitch ----------------
__global__ void k_bn_cross(const float* __restrict__ gam,
                           const float* __restrict__ bet,
                           const float* __restrict__ cu,
                           int layer, int last, float* __restrict__ out) {
    int idx = blockIdx.x * blockDim.x + threadIdx.x;
    if (idx >= NN * 32) return;
    int n = idx >> 5, c4 = idx & 31;
    int f = c4 * 4;
    const float inv = 1.f / (float)NN;

    float4 s1 = *(const float4*)&g_sum[f];
    float4 q1 = *(const float4*)&g_sq[f];
    float4 s2 = *(const float4*)&g_sum[DD + f];
    float4 q2 = *(const float4*)&g_sq[DD + f];

    float4 mu1 = make_float4(s1.x * inv, s1.y * inv, s1.z * inv, s1.w * inv);
    float4 mu2 = make_float4(s2.x * inv, s2.y * inv, s2.z * inv, s2.w * inv);
    float4 rs1 = make_float4(rsqrtf(q1.x * inv - mu1.x * mu1.x + BN_EPS),
                             rsqrtf(q1.y * inv - mu1.y * mu1.y + BN_EPS),
                             rsqrtf(q1.z * inv - mu1.z * mu1.z + BN_EPS),
                             rsqrtf(q1.w * inv - mu1.w * mu1.w + BN_EPS));
    float4 rs2 = make_float4(rsqrtf(q2.x * inv - mu2.x * mu2.x + BN_EPS),
                             rsqrtf(q2.y * inv - mu2.y * mu2.y + BN_EPS),
                             rsqrtf(q2.z * inv - mu2.z * mu2.z + BN_EPS),
                             rsqrtf(q2.w * inv - mu2.w * mu2.w + BN_EPS));

    float4 g1 = *(const float4*)&gam[(0 * LL + layer) * DD + f];
    float4 b1 = *(const float4*)&bet[(0 * LL + layer) * DD + f];
    float4 g2 = *(const float4*)&gam[(1 * LL + layer) * DD + f];
    float4 b2 = *(const float4*)&bet[(1 * LL + layer) * DD + f];

    float4 y1 = ((const float4*)g_Y1)[n * 32 + c4];
    float4 y2 = ((const float4*)g_Y2)[n * 32 + c4];

    y1.x = (y1.x - mu1.x) * rs1.x * g1.x + b1.x;
    y1.y = (y1.y - mu1.y) * rs1.y * g1.y + b1.y;
    y1.z = (y1.z - mu1.z) * rs1.z * g1.z + b1.z;
    y1.w = (y1.w - mu1.w) * rs1.w * g1.w + b1.w;
    y2.x = (y2.x - mu2.x) * rs2.x * g2.x + b2.x;
    y2.y = (y2.y - mu2.y) * rs2.y * g2.y + b2.y;
    y2.z = (y2.z - mu2.z) * rs2.z * g2.z + b2.z;
    y2.w = (y2.w - mu2.w) * rs2.w * g2.w + b2.w;

    if (!last) {
        y1.x = fmaxf(y1.x, 0.f); y1.y = fmaxf(y1.y, 0.f);
        y1.z = fmaxf(y1.z, 0.f); y1.w = fmaxf(y1.w, 0.f);
        y2.x = fmaxf(y2.x, 0.f); y2.y = fmaxf(y2.y, 0.f);
        y2.z = fmaxf(y2.z, 0.f); y2.w = fmaxf(y2.w, 0.f);
    }

    float c00 = cu[layer * 4 + 0], c01 = cu[layer * 4 + 1];
    float c10 = cu[layer * 4 + 2], c11 = cu[layer * 4 + 3];

    float4 n1 = make_float4(c00 * y1.x + c01 * y2.x, c00 * y1.y + c01 * y2.y,
                            c00 * y1.z + c01 * y2.z, c00 * y1.w + c01 * y2.w);
    float4 n2 = make_float4(c10 * n1.x + c11 * y2.x, c10 * n1.y + c11 * y2.y,
                            c10 * n1.z + c11 * y2.z, c10 * n1.w + c11 * y2.w);

    if (last) {
        ((float4*)out)[n * 32 + c4] = n1;
        ((float4*)out)[NN * 32 + n * 32 + c4] = n2;
    } else {
        ((float4*)g_h1)[n * 32 + c4] = n1;
        ((float4*)g_h2)[n * 32 + c4] = n2;
    }
}

// ---------------- launch ----------------
extern "C" void kernel_launch(void* const* d_in, const int* in_sizes, int n_in,
                              void* d_out, int out_size) {
    const int* x = (const int*)d_in[0];
    const int* ei = (const int*)d_in[1];
    const int* ea = (const int*)d_in[2];
    const float* ne1 = (const float*)d_in[3];
    const float* ne2 = (const float*)d_in[4];
    const float* eemb = (const float*)d_in[5];
    const float* eps = (const float*)d_in[6];
    const float* W = (const float*)d_in[7];
    const float* b = (const float*)d_in[8];
    const float* gam = (const float*)d_in[9];
    const float* bet = (const float*)d_in[10];
    const float* cu = (const float*)d_in[11];
    float* out = (float*)d_out;

    static int smem_set = 0;
    if (!smem_set) {
        cudaFuncSetAttribute(k_gemm_tc, cudaFuncAttributeMaxDynamicSharedMemorySize,
                             SM_GEMM_TOTAL);
        smem_set = 1;
    }

    k_zero_deg<<<(NN + 255) / 256, 256>>>();
    k_hist<<<(EE + 255) / 256, 256>>>(ei);
    k_scan<<<1, 1024>>>();
    k_scatter<<<(EE + 255) / 256, 256>>>(ei, ea);
    k_convW<<<(2 * LL * DD * DD + 255) / 256, 256>>>(W);
    k_encode<<<(NN * 32 + 255) / 256, 256>>>(x, ne1, ne2);

    for (int l = 0; l < LL; l++) {
        k_aggregate<<<(NN + 7) / 8, 256>>>(eemb + (0 * LL + l) * EVV * DD,
                                           eemb + (1 * LL + l) * EVV * DD, eps, l);
        dim3 gg((NN + 127) / 128, 2);
        k_gemm_tc<<<gg, 256, SM_GEMM_TOTAL>>>(b, l);
        k_bn_cross<<<(NN * 32 + 255) / 256, 256>>>(gam, bet, cu, l, (l == LL - 1) ? 1 : 0, out);
    }
}